// round 10
// baseline (speedup 1.0000x reference)
#include <cuda_runtime.h>
#include <cuda_bf16.h>
#include <float.h>
#include <math.h>
#include <stdint.h>

// Problem constants
#define Bc   4
#define Tc   4096
#define DINc 1024
#define Hc   16
#define Dc   64
#define TCc  128            // t-chunk (M) per block
#define NCc  (Tc / TCc)     // 32 chunks
#define KC   32             // K per stage
#define NST  (DINc / KC)    // 32 stages

// SMEM stage: 4 matrices of [128 rows][32 bf16] (64 B rows, XOR-swizzled)
#define MAT_B  (128 * 64)                  // 8192
#define A0_OFF 0
#define A1_OFF MAT_B
#define B0_OFF (2 * MAT_B)
#define B1_OFF (3 * MAT_B)
#define STG_B  (4 * MAT_B)                 // 32768
#define NBUF   3
#define SMEM_DYN (1024 + NBUF * STG_B)     // 99328 -> 2 CTAs/SM

// Scratch (allocation-free rule: __device__ globals)
__device__ __nv_bfloat16 g_A0[Bc * Tc * DINc];    // inputs hi split [b*t][k]
__device__ __nv_bfloat16 g_A1[Bc * Tc * DINc];    // inputs lo split
__device__ __nv_bfloat16 g_W0[Hc * 128 * DINc];   // W hi split [h][n][k]
__device__ __nv_bfloat16 g_W1[Hc * 128 * DINc];   // W lo split
__device__ float g_Sm[Bc * Hc * Tc];
__device__ float g_Su[Bc * Hc * Tc];
__device__ float g_Sw[Bc * Hc * Tc * Dc];
__device__ float g_Pm[Bc * Hc * NCc];
__device__ float g_Pu[Bc * Hc * NCc];
__device__ float g_Pw[Bc * Hc * NCc * Dc];

// ---------------- PTX helpers (baseline sm_80+ features only) ----------------
__device__ __forceinline__ uint32_t smem_u32(const void* p) {
    uint32_t a;
    asm("{ .reg .u64 t; cvta.to.shared.u64 t, %1; cvt.u32.u64 %0, t; }" : "=r"(a) : "l"(p));
    return a;
}
__device__ __forceinline__ void cp16(uint32_t dst, const void* src) {
    asm volatile("cp.async.cg.shared.global [%0], [%1], 16;" :: "r"(dst), "l"(src));
}
#define CP_COMMIT() asm volatile("cp.async.commit_group;" ::: "memory")
#define CP_WAIT1()  asm volatile("cp.async.wait_group 1;" ::: "memory")
#define CP_WAIT0()  asm volatile("cp.async.wait_group 0;" ::: "memory")

#define LDSM4(r, addr) \
    asm volatile("ldmatrix.sync.aligned.m8n8.x4.shared.b16 {%0,%1,%2,%3}, [%4];" \
        : "=r"((r)[0]), "=r"((r)[1]), "=r"((r)[2]), "=r"((r)[3]) : "r"(addr))

#define MMA_BF16(d, a0, a1, a2, a3, b0, b1) \
    asm volatile("mma.sync.aligned.m16n8k16.row.col.f32.bf16.bf16.f32 " \
        "{%0,%1,%2,%3}, {%4,%5,%6,%7}, {%8,%9}, {%0,%1,%2,%3};" \
        : "+f"((d)[0]), "+f"((d)[1]), "+f"((d)[2]), "+f"((d)[3]) \
        : "r"(a0), "r"(a1), "r"(a2), "r"(a3), "r"(b0), "r"(b1))

__device__ __forceinline__ unsigned bf2u(__nv_bfloat162 v) {
    return *reinterpret_cast<unsigned*>(&v);
}
// XOR swizzle: byte offset of 16B chunk c in row r (64 B pitch)
__device__ __forceinline__ uint32_t swz(int row, int c) {
    return (uint32_t)(row * 64 + ((c ^ ((row >> 1) & 3)) << 4));
}

// ---------------------------------------------------------------------------
// prep: split inputs AND W into bf16 hi/lo. One launch for both.
// Blocks [0, 16384): A.   Blocks [16384, 18432): W (transposed to [h][n][k]).
// ---------------------------------------------------------------------------
__global__ __launch_bounds__(256)
void prep_split(const float* __restrict__ A, const float* __restrict__ W)
{
    if (blockIdx.x < 16384) {
        size_t i4 = ((size_t)blockIdx.x * 256 + threadIdx.x) * 4;
        float4 v = *reinterpret_cast<const float4*>(A + i4);
        float h0 = __bfloat162float(__float2bfloat16_rn(v.x));
        float h1 = __bfloat162float(__float2bfloat16_rn(v.y));
        float h2 = __bfloat162float(__float2bfloat16_rn(v.z));
        float h3 = __bfloat162float(__float2bfloat16_rn(v.w));
        uint2 hi, lo;
        hi.x = bf2u(__floats2bfloat162_rn(v.x, v.y));
        hi.y = bf2u(__floats2bfloat162_rn(v.z, v.w));
        lo.x = bf2u(__floats2bfloat162_rn(v.x - h0, v.y - h1));
        lo.y = bf2u(__floats2bfloat162_rn(v.z - h2, v.w - h3));
        *reinterpret_cast<uint2*>(reinterpret_cast<char*>(g_A0) + i4 * 2) = hi;
        *reinterpret_cast<uint2*>(reinterpret_cast<char*>(g_A1) + i4 * 2) = lo;
    } else {
        int idx = (blockIdx.x - 16384) * 256 + threadIdx.x;   // 0..524287
        int jg  = idx & 31;
        int h   = (idx >> 5) & 15;
        int k   = idx >> 9;
        float4 w = *reinterpret_cast<const float4*>(W + (size_t)k * (Hc * Dc * 2) + h * 128 + jg * 4);
        float x[4] = {w.x, w.y, w.z, w.w};
        #pragma unroll
        for (int e = 0; e < 4; ++e) {
            __nv_bfloat16 hb = __float2bfloat16_rn(x[e]);
            float hf = __bfloat162float(hb);
            __nv_bfloat16 lb = __float2bfloat16_rn(x[e] - hf);
            size_t o = ((size_t)h * 128 + jg * 4 + e) * DINc + k;
            g_W0[o] = hb;
            g_W1[o] = lb;
        }
    }
}

// ---------------------------------------------------------------------------
// Kernel 1: bf16x2-split HMMA GEMM (kv = relu(A@W)) + st=q.k + local scan.
// M=128, N=128, K=1024. 8 warps 4x2, warp tile 32x64. 3-stage cp.async
// pipeline, KC=32, XOR-swizzled 64B rows, 2 CTAs/SM.
// ---------------------------------------------------------------------------
__global__ __launch_bounds__(256, 2)
void k1_gemm_scan(const float* __restrict__ Q)
{
    extern __shared__ __align__(1024) char dsm[];
    const int c = blockIdx.x, h = blockIdx.y, b = blockIdx.z;
    const int t0 = c * TCc;
    const int tid = threadIdx.x;
    const int wid = tid >> 5, lane = tid & 31;
    const int wm = wid >> 1;           // 0..3 (M groups of 32)
    const int wn = wid & 1;            // 0..1 (N groups of 64)
    const uint32_t sb = smem_u32(dsm);

    float* qS = (float*)(dsm + 32);
    if (tid < 64) qS[tid] = Q[h * Dc + tid];

    const __nv_bfloat16* Ab0 = g_A0 + ((size_t)b * Tc + t0) * DINc;
    const __nv_bfloat16* Ab1 = g_A1 + ((size_t)b * Tc + t0) * DINc;
    const __nv_bfloat16* Wb0 = g_W0 + (size_t)h * 128 * DINc;
    const __nv_bfloat16* Wb1 = g_W1 + (size_t)h * 128 * DINc;

    // cp.async mapping: per matrix, thread does ids {2*tid, 2*tid+1}:
    // row = id>>2 (0..127), chunk c = id&3. Two chunks of one row per thread.
    const int ld_row = tid >> 1;                 // (2*tid)>>2
    const int ld_c0  = (tid & 1) * 2;            // 0 or 2

    float acc[2][8][4];
    #pragma unroll
    for (int mt = 0; mt < 2; ++mt)
        #pragma unroll
        for (int nt = 0; nt < 8; ++nt)
            #pragma unroll
            for (int e = 0; e < 4; ++e) acc[mt][nt][e] = 0.f;

    // helper lambda-ish macro to issue one stage's loads
    #define ISSUE_STAGE(SIDX)                                                     \
    do {                                                                          \
        uint32_t stg_ = sb + 1024 + ((SIDX) % NBUF) * STG_B;                      \
        const int k0_ = (SIDX) * KC;                                              \
        size_t so0 = (size_t)ld_row * DINc + k0_ + ld_c0 * 8;                     \
        uint32_t d0 = stg_ + swz(ld_row, ld_c0);                                  \
        uint32_t d1 = stg_ + swz(ld_row, ld_c0 + 1);                              \
        cp16(d0 + A0_OFF, Ab0 + so0);  cp16(d1 + A0_OFF, Ab0 + so0 + 8);          \
        cp16(d0 + A1_OFF, Ab1 + so0);  cp16(d1 + A1_OFF, Ab1 + so0 + 8);          \
        cp16(d0 + B0_OFF, Wb0 + so0);  cp16(d1 + B0_OFF, Wb0 + so0 + 8);          \
        cp16(d0 + B1_OFF, Wb1 + so0);  cp16(d1 + B1_OFF, Wb1 + so0 + 8);          \
        CP_COMMIT();                                                              \
    } while (0)

    ISSUE_STAGE(0);
    ISSUE_STAGE(1);

    for (int i = 0; i < NST; ++i) {
        if (i < NST - 1) CP_WAIT1(); else CP_WAIT0();
        __syncthreads();                 // all warps done with stage i-1's buffer
        if (i + 2 < NST) ISSUE_STAGE(i + 2);

        const uint32_t stg = sb + 1024 + (i % NBUF) * STG_B;
        #pragma unroll
        for (int ks = 0; ks < 2; ++ks) {
            uint32_t aH[2][4], aL[2][4];
            #pragma unroll
            for (int mt = 0; mt < 2; ++mt) {
                int row = wm * 32 + mt * 16 + (lane & 15);
                int cc = ks * 2 + (lane >> 4);
                uint32_t ad = stg + swz(row, cc);
                LDSM4(aH[mt], ad + A0_OFF);
                LDSM4(aL[mt], ad + A1_OFF);
            }
            #pragma unroll
            for (int nt2 = 0; nt2 < 4; ++nt2) {
                int row = wn * 64 + nt2 * 16 + (lane & 7) + ((lane >> 4) << 3);
                int cc = ks * 2 + ((lane >> 3) & 1);
                uint32_t bd = stg + swz(row, cc);
                uint32_t rH[4], rL[4];
                LDSM4(rH, bd + B0_OFF);
                LDSM4(rL, bd + B1_OFF);
                #pragma unroll
                for (int mt = 0; mt < 2; ++mt) {
                    float* d0 = acc[mt][2 * nt2];
                    float* d1 = acc[mt][2 * nt2 + 1];
                    MMA_BF16(d0, aH[mt][0], aH[mt][1], aH[mt][2], aH[mt][3], rH[0], rH[1]);
                    MMA_BF16(d0, aH[mt][0], aH[mt][1], aH[mt][2], aH[mt][3], rL[0], rL[1]);
                    MMA_BF16(d0, aL[mt][0], aL[mt][1], aL[mt][2], aL[mt][3], rH[0], rH[1]);
                    MMA_BF16(d1, aH[mt][0], aH[mt][1], aH[mt][2], aH[mt][3], rH[2], rH[3]);
                    MMA_BF16(d1, aH[mt][0], aH[mt][1], aH[mt][2], aH[mt][3], rL[2], rL[3]);
                    MMA_BF16(d1, aL[mt][0], aL[mt][1], aL[mt][2], aL[mt][3], rH[2], rH[3]);
                }
            }
        }
    }
    __syncthreads();                     // mainloop smem free before epilogue reuse

    // ---------------- epilogue: relu, st = q.k partials, Vs ----------------
    float* Vs     = (float*)(dsm + 1024);                      // [128][65]
    float* stS    = (float*)(dsm + 1024 + 128 * 65 * 4);       // [128]
    float* stPart = (float*)(dsm + 1024 + 128 * 65 * 4 + 512); // [128][8]

    const int g = lane >> 2;
    const int dq = lane & 3;
    #pragma unroll
    for (int mt = 0; mt < 2; ++mt) {
        const int m0 = wm * 32 + mt * 16 + g;
        float stp0 = 0.f, stp1 = 0.f;
        #pragma unroll
        for (int nt = 0; nt < 8; ++nt) {
            int d = wn * 32 + nt * 4 + dq;
            float qd = qS[d];
            float k0_ = fmaxf(acc[mt][nt][0], 0.f);
            float v0_ = fmaxf(acc[mt][nt][1], 0.f);
            float k1_ = fmaxf(acc[mt][nt][2], 0.f);
            float v1_ = fmaxf(acc[mt][nt][3], 0.f);
            stp0 = fmaf(qd, k0_, stp0);
            stp1 = fmaf(qd, k1_, stp1);
            Vs[m0 * 65 + d]       = v0_;
            Vs[(m0 + 8) * 65 + d] = v1_;
        }
        stPart[m0 * 8 + wn * 4 + dq]       = stp0;
        stPart[(m0 + 8) * 8 + wn * 4 + dq] = stp1;
    }
    __syncthreads();

    if (tid < 128) {
        float s = 0.f;
        #pragma unroll
        for (int x = 0; x < 8; ++x) s += stPart[tid * 8 + x];
        stS[tid] = s;
    }
    __syncthreads();

    // ---------------- sequential local scan over the chunk ----------------
    if (tid < Dc) {
        const int sl = tid;
        const size_t baseT = ((size_t)(b * Hc + h)) * Tc + t0;
        float m = -FLT_MAX, u = 0.f, w = 0.f;
        for (int t = 0; t < TCc; ++t) {
            float st = stS[t];
            float mn = fmaxf(m, st);
            float ea = __expf(m - mn);
            float eb = __expf(st - mn);
            u = u * ea + eb;
            w = fmaf(w, ea, Vs[t * 65 + sl] * eb);
            m = mn;
            g_Sw[(baseT + t) * Dc + sl] = w;
            if (sl == 0) { g_Sm[baseT + t] = m; g_Su[baseT + t] = u; }
        }
    }
}

// ---------------------------------------------------------------------------
// Kernel 2: exclusive prefix over chunk summaries per (b,h).
// Preload all 32 summaries with independent loads (MLP), then combine.
// ---------------------------------------------------------------------------
__global__ void k2_prefix()
{
    const int bh = blockIdx.x;
    const int lane = threadIdx.x;
    const size_t baseT = (size_t)bh * Tc;
    const size_t baseC = (size_t)bh * NCc;

    float sm[NCc], su[NCc], sw[NCc];
    #pragma unroll
    for (int cI = 0; cI < NCc; ++cI) {
        int t = cI * TCc + (TCc - 1);
        sm[cI] = g_Sm[baseT + t];
        su[cI] = g_Su[baseT + t];
        sw[cI] = g_Sw[(baseT + t) * Dc + lane];
    }
    float m = -FLT_MAX, u = 0.f, w = 0.f;
    #pragma unroll
    for (int cI = 0; cI < NCc; ++cI) {
        g_Pw[(baseC + cI) * Dc + lane] = w;
        if (lane == 0) { g_Pm[baseC + cI] = m; g_Pu[baseC + cI] = u; }
        float mn = fmaxf(m, sm[cI]);
        float ea = __expf(m - mn);
        float eb = __expf(sm[cI] - mn);
        u = u * ea + su[cI] * eb;
        w = fmaf(w, ea, sw[cI] * eb);
        m = mn;
    }
}

// ---------------------------------------------------------------------------
// Kernel 3: combine prefix + local, h = w/u, sum over heads.
// ---------------------------------------------------------------------------
__global__ __launch_bounds__(256)
void k3_final(float* __restrict__ out)
{
    const int lane = threadIdx.x & 63;
    const size_t rowG = (size_t)blockIdx.x * 4 + (threadIdx.x >> 6);
    const int b = (int)(rowG >> 12);
    const int t = (int)(rowG & 4095);
    const int cI = t / TCc;

    float acc = 0.f;
    #pragma unroll
    for (int h = 0; h < Hc; ++h) {
        const size_t bh = (size_t)b * Hc + h;
        const size_t ci = bh * NCc + cI;
        const size_t ti = bh * Tc + t;
        float pm = g_Pm[ci], pu = g_Pu[ci];
        float pw = g_Pw[ci * Dc + lane];
        float lm = g_Sm[ti], lu = g_Su[ti];
        float lw = g_Sw[ti * Dc + lane];
        float mn = fmaxf(pm, lm);
        float ea = __expf(pm - mn);
        float eb = __expf(lm - mn);
        float u = pu * ea + lu * eb;
        float w = fmaf(pw, ea, lw * eb);
        acc += w / u;
    }
    out[rowG * Dc + lane] = acc;
}

// ---------------------------------------------------------------------------
extern "C" void kernel_launch(void* const* d_in, const int* in_sizes, int n_in,
                              void* d_out, int out_size)
{
    const float* A = nullptr;
    const float* W = nullptr;
    const float* Q = nullptr;
    for (int i = 0; i < n_in; ++i) {
        if      (in_sizes[i] == Bc * Tc * DINc)      A = (const float*)d_in[i];
        else if (in_sizes[i] == DINc * Hc * Dc * 2)  W = (const float*)d_in[i];
        else if (in_sizes[i] == Hc * Dc)             Q = (const float*)d_in[i];
    }
    float* out = (float*)d_out;

    cudaFuncSetAttribute(k1_gemm_scan, cudaFuncAttributeMaxDynamicSharedMemorySize, SMEM_DYN);

    prep_split<<<16384 + 2048, 256>>>(A, W);
    dim3 g1(NCc, Hc, Bc);
    k1_gemm_scan<<<g1, 256, SMEM_DYN>>>(Q);
    k2_prefix<<<Bc * Hc, Dc>>>();
    k3_final<<<(Bc * Tc) / 4, 256>>>(out);
}

// round 11
// speedup vs baseline: 1.0471x; 1.0471x over previous
#include <cuda_runtime.h>
#include <cuda_bf16.h>
#include <float.h>
#include <math.h>
#include <stdint.h>

// Problem constants
#define Bc   4
#define Tc   4096
#define DINc 1024
#define Hc   16
#define Dc   64
#define TCc  128            // t-chunk (M) per block
#define NCc  (Tc / TCc)     // 32 chunks
#define KC   32             // K per stage
#define NST  (DINc / KC)    // 32 stages

// SMEM stage: 4 matrices of [128 rows][32 bf16] (64 B rows, XOR-swizzled)
#define MAT_B  (128 * 64)                  // 8192
#define A0_OFF 0
#define A1_OFF MAT_B
#define B0_OFF (2 * MAT_B)
#define B1_OFF (3 * MAT_B)
#define STG_B  (4 * MAT_B)                 // 32768
#define NBUF   3
#define SMEM_DYN (1024 + NBUF * STG_B)     // 99328 -> 2 CTAs/SM

// Scratch (allocation-free rule: __device__ globals)
__device__ __nv_bfloat16 g_A0[Bc * Tc * DINc];    // inputs hi split [b*t][k]
__device__ __nv_bfloat16 g_A1[Bc * Tc * DINc];    // inputs lo split
__device__ __nv_bfloat16 g_W0[Hc * 128 * DINc];   // W hi split [h][n][k]
__device__ __nv_bfloat16 g_W1[Hc * 128 * DINc];   // W lo split
__device__ float g_Sm[Bc * Hc * Tc];
__device__ float g_Su[Bc * Hc * Tc];
__device__ float g_Sw[Bc * Hc * Tc * Dc];
__device__ float g_Pm[Bc * Hc * NCc];
__device__ float g_Pu[Bc * Hc * NCc];
__device__ float g_Pw[Bc * Hc * NCc * Dc];

// ---------------- PTX helpers (baseline sm_80+ features only) ----------------
__device__ __forceinline__ uint32_t smem_u32(const void* p) {
    uint32_t a;
    asm("{ .reg .u64 t; cvta.to.shared.u64 t, %1; cvt.u32.u64 %0, t; }" : "=r"(a) : "l"(p));
    return a;
}
__device__ __forceinline__ void cp16(uint32_t dst, const void* src) {
    asm volatile("cp.async.cg.shared.global [%0], [%1], 16;" :: "r"(dst), "l"(src));
}
#define CP_COMMIT() asm volatile("cp.async.commit_group;" ::: "memory")
#define CP_WAIT1()  asm volatile("cp.async.wait_group 1;" ::: "memory")
#define CP_WAIT0()  asm volatile("cp.async.wait_group 0;" ::: "memory")

#define LDSM4(r, addr) \
    asm volatile("ldmatrix.sync.aligned.m8n8.x4.shared.b16 {%0,%1,%2,%3}, [%4];" \
        : "=r"((r)[0]), "=r"((r)[1]), "=r"((r)[2]), "=r"((r)[3]) : "r"(addr))

#define MMA_BF16(d, a0, a1, a2, a3, b0, b1) \
    asm volatile("mma.sync.aligned.m16n8k16.row.col.f32.bf16.bf16.f32 " \
        "{%0,%1,%2,%3}, {%4,%5,%6,%7}, {%8,%9}, {%0,%1,%2,%3};" \
        : "+f"((d)[0]), "+f"((d)[1]), "+f"((d)[2]), "+f"((d)[3]) \
        : "r"(a0), "r"(a1), "r"(a2), "r"(a3), "r"(b0), "r"(b1))

__device__ __forceinline__ unsigned bf2u(__nv_bfloat162 v) {
    return *reinterpret_cast<unsigned*>(&v);
}
// XOR swizzle: byte offset of 16B chunk c in row r (64 B pitch)
__device__ __forceinline__ uint32_t swz(int row, int c) {
    return (uint32_t)(row * 64 + ((c ^ ((row >> 1) & 3)) << 4));
}

// ---------------------------------------------------------------------------
// prep: split inputs AND W into bf16 hi/lo. One launch for both.
// ---------------------------------------------------------------------------
__global__ __launch_bounds__(256)
void prep_split(const float* __restrict__ A, const float* __restrict__ W)
{
    if (blockIdx.x < 16384) {
        size_t i4 = ((size_t)blockIdx.x * 256 + threadIdx.x) * 4;
        float4 v = *reinterpret_cast<const float4*>(A + i4);
        float h0 = __bfloat162float(__float2bfloat16_rn(v.x));
        float h1 = __bfloat162float(__float2bfloat16_rn(v.y));
        float h2 = __bfloat162float(__float2bfloat16_rn(v.z));
        float h3 = __bfloat162float(__float2bfloat16_rn(v.w));
        uint2 hi, lo;
        hi.x = bf2u(__floats2bfloat162_rn(v.x, v.y));
        hi.y = bf2u(__floats2bfloat162_rn(v.z, v.w));
        lo.x = bf2u(__floats2bfloat162_rn(v.x - h0, v.y - h1));
        lo.y = bf2u(__floats2bfloat162_rn(v.z - h2, v.w - h3));
        *reinterpret_cast<uint2*>(reinterpret_cast<char*>(g_A0) + i4 * 2) = hi;
        *reinterpret_cast<uint2*>(reinterpret_cast<char*>(g_A1) + i4 * 2) = lo;
    } else {
        int idx = (blockIdx.x - 16384) * 256 + threadIdx.x;   // 0..524287
        int jg  = idx & 31;
        int h   = (idx >> 5) & 15;
        int k   = idx >> 9;
        float4 w = *reinterpret_cast<const float4*>(W + (size_t)k * (Hc * Dc * 2) + h * 128 + jg * 4);
        float x[4] = {w.x, w.y, w.z, w.w};
        #pragma unroll
        for (int e = 0; e < 4; ++e) {
            __nv_bfloat16 hb = __float2bfloat16_rn(x[e]);
            float hf = __bfloat162float(hb);
            __nv_bfloat16 lb = __float2bfloat16_rn(x[e] - hf);
            size_t o = ((size_t)h * 128 + jg * 4 + e) * DINc + k;
            g_W0[o] = hb;
            g_W1[o] = lb;
        }
    }
}

// ---------------------------------------------------------------------------
// Kernel 1: bf16x2-split HMMA GEMM (kv = relu(A@W)) + st=q.k + local scan.
// Grid (H, chunk, batch): same-A CTAs launch-adjacent for L2 reuse.
// MMA issue order term-major: 4 independent accumulators between RAW reuse.
// ---------------------------------------------------------------------------
__global__ __launch_bounds__(256, 2)
void k1_gemm_scan(const float* __restrict__ Q)
{
    extern __shared__ __align__(1024) char dsm[];
    const int h = blockIdx.x, c = blockIdx.y, b = blockIdx.z;
    const int t0 = c * TCc;
    const int tid = threadIdx.x;
    const int wid = tid >> 5, lane = tid & 31;
    const int wm = wid >> 1;           // 0..3 (M groups of 32)
    const int wn = wid & 1;            // 0..1 (N groups of 64)
    const uint32_t sb = smem_u32(dsm);

    float* qS = (float*)(dsm + 32);
    if (tid < 64) qS[tid] = Q[h * Dc + tid];

    const __nv_bfloat16* Ab0 = g_A0 + ((size_t)b * Tc + t0) * DINc;
    const __nv_bfloat16* Ab1 = g_A1 + ((size_t)b * Tc + t0) * DINc;
    const __nv_bfloat16* Wb0 = g_W0 + (size_t)h * 128 * DINc;
    const __nv_bfloat16* Wb1 = g_W1 + (size_t)h * 128 * DINc;

    const int ld_row = tid >> 1;
    const int ld_c0  = (tid & 1) * 2;

    float acc[2][8][4];
    #pragma unroll
    for (int mt = 0; mt < 2; ++mt)
        #pragma unroll
        for (int nt = 0; nt < 8; ++nt)
            #pragma unroll
            for (int e = 0; e < 4; ++e) acc[mt][nt][e] = 0.f;

    #define ISSUE_STAGE(SIDX)                                                     \
    do {                                                                          \
        uint32_t stg_ = sb + 1024 + ((SIDX) % NBUF) * STG_B;                      \
        const int k0_ = (SIDX) * KC;                                              \
        size_t so0 = (size_t)ld_row * DINc + k0_ + ld_c0 * 8;                     \
        uint32_t d0 = stg_ + swz(ld_row, ld_c0);                                  \
        uint32_t d1 = stg_ + swz(ld_row, ld_c0 + 1);                              \
        cp16(d0 + A0_OFF, Ab0 + so0);  cp16(d1 + A0_OFF, Ab0 + so0 + 8);          \
        cp16(d0 + A1_OFF, Ab1 + so0);  cp16(d1 + A1_OFF, Ab1 + so0 + 8);          \
        cp16(d0 + B0_OFF, Wb0 + so0);  cp16(d1 + B0_OFF, Wb0 + so0 + 8);          \
        cp16(d0 + B1_OFF, Wb1 + so0);  cp16(d1 + B1_OFF, Wb1 + so0 + 8);          \
        CP_COMMIT();                                                              \
    } while (0)

    ISSUE_STAGE(0);
    ISSUE_STAGE(1);

    for (int i = 0; i < NST; ++i) {
        if (i < NST - 1) CP_WAIT1(); else CP_WAIT0();
        __syncthreads();
        if (i + 2 < NST) ISSUE_STAGE(i + 2);

        const uint32_t stg = sb + 1024 + (i % NBUF) * STG_B;
        #pragma unroll
        for (int ks = 0; ks < 2; ++ks) {
            uint32_t aH[2][4], aL[2][4];
            #pragma unroll
            for (int mt = 0; mt < 2; ++mt) {
                int row = wm * 32 + mt * 16 + (lane & 15);
                int cc = ks * 2 + (lane >> 4);
                uint32_t ad = stg + swz(row, cc);
                LDSM4(aH[mt], ad + A0_OFF);
                LDSM4(aL[mt], ad + A1_OFF);
            }
            #pragma unroll
            for (int nt2 = 0; nt2 < 4; ++nt2) {
                int row = wn * 64 + nt2 * 16 + (lane & 7) + ((lane >> 4) << 3);
                int cc = ks * 2 + ((lane >> 3) & 1);
                uint32_t bd = stg + swz(row, cc);
                uint32_t rH[4], rL[4];
                LDSM4(rH, bd + B0_OFF);
                LDSM4(rL, bd + B1_OFF);
                // term-major order: 4 independent accumulators between
                // reuses of the same accumulator (breaks HMMA RAW chains).
                #pragma unroll
                for (int mt = 0; mt < 2; ++mt) {
                    MMA_BF16(acc[mt][2 * nt2],     aH[mt][0], aH[mt][1], aH[mt][2], aH[mt][3], rH[0], rH[1]);
                    MMA_BF16(acc[mt][2 * nt2 + 1], aH[mt][0], aH[mt][1], aH[mt][2], aH[mt][3], rH[2], rH[3]);
                }
                #pragma unroll
                for (int mt = 0; mt < 2; ++mt) {
                    MMA_BF16(acc[mt][2 * nt2],     aH[mt][0], aH[mt][1], aH[mt][2], aH[mt][3], rL[0], rL[1]);
                    MMA_BF16(acc[mt][2 * nt2 + 1], aH[mt][0], aH[mt][1], aH[mt][2], aH[mt][3], rL[2], rL[3]);
                }
                #pragma unroll
                for (int mt = 0; mt < 2; ++mt) {
                    MMA_BF16(acc[mt][2 * nt2],     aL[mt][0], aL[mt][1], aL[mt][2], aL[mt][3], rH[0], rH[1]);
                    MMA_BF16(acc[mt][2 * nt2 + 1], aL[mt][0], aL[mt][1], aL[mt][2], aL[mt][3], rH[2], rH[3]);
                }
            }
        }
    }
    __syncthreads();

    // ---------------- epilogue: relu, st = q.k partials, Vs ----------------
    float* Vs     = (float*)(dsm + 1024);                      // [128][65]
    float* stS    = (float*)(dsm + 1024 + 128 * 65 * 4);       // [128]
    float* stPart = (float*)(dsm + 1024 + 128 * 65 * 4 + 512); // [128][8]

    const int g = lane >> 2;
    const int dq = lane & 3;
    #pragma unroll
    for (int mt = 0; mt < 2; ++mt) {
        const int m0 = wm * 32 + mt * 16 + g;
        float stp0 = 0.f, stp1 = 0.f;
        #pragma unroll
        for (int nt = 0; nt < 8; ++nt) {
            int d = wn * 32 + nt * 4 + dq;
            float qd = qS[d];
            float k0_ = fmaxf(acc[mt][nt][0], 0.f);
            float v0_ = fmaxf(acc[mt][nt][1], 0.f);
            float k1_ = fmaxf(acc[mt][nt][2], 0.f);
            float v1_ = fmaxf(acc[mt][nt][3], 0.f);
            stp0 = fmaf(qd, k0_, stp0);
            stp1 = fmaf(qd, k1_, stp1);
            Vs[m0 * 65 + d]       = v0_;
            Vs[(m0 + 8) * 65 + d] = v1_;
        }
        stPart[m0 * 8 + wn * 4 + dq]       = stp0;
        stPart[(m0 + 8) * 8 + wn * 4 + dq] = stp1;
    }
    __syncthreads();

    if (tid < 128) {
        float s = 0.f;
        #pragma unroll
        for (int x = 0; x < 8; ++x) s += stPart[tid * 8 + x];
        stS[tid] = s;
    }
    __syncthreads();

    // ---------------- sequential local scan over the chunk ----------------
    if (tid < Dc) {
        const int sl = tid;
        const size_t baseT = ((size_t)(b * Hc + h)) * Tc + t0;
        float m = -FLT_MAX, u = 0.f, w = 0.f;
        for (int t = 0; t < TCc; ++t) {
            float st = stS[t];
            float mn = fmaxf(m, st);
            float ea = __expf(m - mn);
            float eb = __expf(st - mn);
            u = u * ea + eb;
            w = fmaf(w, ea, Vs[t * 65 + sl] * eb);
            m = mn;
            g_Sw[(baseT + t) * Dc + sl] = w;
            if (sl == 0) { g_Sm[baseT + t] = m; g_Su[baseT + t] = u; }
        }
    }
}

// ---------------------------------------------------------------------------
// Kernel 2: exclusive prefix over chunk summaries per (b,h).
// ---------------------------------------------------------------------------
__global__ void k2_prefix()
{
    const int bh = blockIdx.x;
    const int lane = threadIdx.x;
    const size_t baseT = (size_t)bh * Tc;
    const size_t baseC = (size_t)bh * NCc;

    float sm[NCc], su[NCc], sw[NCc];
    #pragma unroll
    for (int cI = 0; cI < NCc; ++cI) {
        int t = cI * TCc + (TCc - 1);
        sm[cI] = g_Sm[baseT + t];
        su[cI] = g_Su[baseT + t];
        sw[cI] = g_Sw[(baseT + t) * Dc + lane];
    }
    float m = -FLT_MAX, u = 0.f, w = 0.f;
    #pragma unroll
    for (int cI = 0; cI < NCc; ++cI) {
        g_Pw[(baseC + cI) * Dc + lane] = w;
        if (lane == 0) { g_Pm[baseC + cI] = m; g_Pu[baseC + cI] = u; }
        float mn = fmaxf(m, sm[cI]);
        float ea = __expf(m - mn);
        float eb = __expf(sm[cI] - mn);
        u = u * ea + su[cI] * eb;
        w = fmaf(w, ea, sw[cI] * eb);
        m = mn;
    }
}

// ---------------------------------------------------------------------------
// Kernel 3: combine prefix + local, h = w/u, sum over heads.
// Block = 4 rows sharing (b, chunk). Scalars + Pw staged in smem once.
// ---------------------------------------------------------------------------
__global__ __launch_bounds__(256)
void k3_final(float* __restrict__ out)
{
    __shared__ float sPw[Hc][Dc];
    __shared__ float sPm[Hc], sPu[Hc];
    __shared__ float sSm[4][Hc], sSu[4][Hc];

    const int tid = threadIdx.x;
    const size_t row0 = (size_t)blockIdx.x * 4;      // 4 rows, same b, same chunk
    const int b  = (int)(row0 >> 12);
    const int t0 = (int)(row0 & 4095);
    const int cI = t0 / TCc;

    // cooperative staging
    for (int i = tid; i < Hc * Dc; i += 256) {
        int hh = i >> 6, d = i & 63;
        sPw[hh][d] = g_Pw[(((size_t)b * Hc + hh) * NCc + cI) * Dc + d];
    }
    if (tid < Hc) {
        size_t ci = ((size_t)b * Hc + tid) * NCc + cI;
        sPm[tid] = g_Pm[ci];
        sPu[tid] = g_Pu[ci];
    } else if (tid < 16 + 64) {
        int j = tid - 16; int r = j >> 4, hh = j & 15;
        sSm[r][hh] = g_Sm[((size_t)b * Hc + hh) * Tc + t0 + r];
    } else if (tid < 80 + 64) {
        int j = tid - 80; int r = j >> 4, hh = j & 15;
        sSu[r][hh] = g_Su[((size_t)b * Hc + hh) * Tc + t0 + r];
    }
    __syncthreads();

    const int r = tid >> 6, lane = tid & 63;
    const int t = t0 + r;
    float acc = 0.f;
    #pragma unroll
    for (int hh = 0; hh < Hc; ++hh) {
        size_t ti = ((size_t)b * Hc + hh) * Tc + t;
        float lw = g_Sw[ti * Dc + lane];
        float pm = sPm[hh], pu = sPu[hh];
        float lm = sSm[r][hh], lu = sSu[r][hh];
        float mn = fmaxf(pm, lm);
        float ea = __expf(pm - mn);
        float eb = __expf(lm - mn);
        float u = pu * ea + lu * eb;
        float w = fmaf(sPw[hh][lane], ea, lw * eb);
        acc += __fdividef(w, u);
    }
    out[(row0 + r) * Dc + lane] = acc;
}

// ---------------------------------------------------------------------------
extern "C" void kernel_launch(void* const* d_in, const int* in_sizes, int n_in,
                              void* d_out, int out_size)
{
    const float* A = nullptr;
    const float* W = nullptr;
    const float* Q = nullptr;
    for (int i = 0; i < n_in; ++i) {
        if      (in_sizes[i] == Bc * Tc * DINc)      A = (const float*)d_in[i];
        else if (in_sizes[i] == DINc * Hc * Dc * 2)  W = (const float*)d_in[i];
        else if (in_sizes[i] == Hc * Dc)             Q = (const float*)d_in[i];
    }
    float* out = (float*)d_out;

    cudaFuncSetAttribute(k1_gemm_scan, cudaFuncAttributeMaxDynamicSharedMemorySize, SMEM_DYN);

    prep_split<<<16384 + 2048, 256>>>(A, W);
    dim3 g1(Hc, NCc, Bc);
    k1_gemm_scan<<<g1, 256, SMEM_DYN>>>(Q);
    k2_prefix<<<Bc * Hc, Dc>>>();
    k3_final<<<(Bc * Tc) / 4, 256>>>(out);
}

// round 14
// speedup vs baseline: 1.3885x; 1.3260x over previous
#include <cuda_runtime.h>
#include <cuda_bf16.h>
#include <cuda_fp16.h>
#include <float.h>
#include <math.h>
#include <stdint.h>

// Problem constants
#define Bc   4
#define Tc   4096
#define DINc 1024
#define Hc   16
#define Dc   64
#define TCc  128            // t-chunk (M) per block
#define NCc  (Tc / TCc)     // 32 chunks
#define KC   32             // K per stage
#define NST  (DINc / KC)    // 32 stages

// SMEM stage: 3 matrices of [128 rows][32 fp16] (64 B rows, XOR-swizzled)
#define MAT_B  (128 * 64)                  // 8192
#define A_OFF  0
#define B0_OFF MAT_B
#define B1_OFF (2 * MAT_B)
#define STG_B  (3 * MAT_B)                 // 24576
#define NBUF   4
#define SMEM_DYN (1024 + NBUF * STG_B)     // 99328 -> 2 CTAs/SM

// Scratch (allocation-free rule: __device__ globals)
__device__ __half g_Ah[Bc * Tc * DINc];           // inputs fp16 [b*t][k]
__device__ __half g_W0[Hc * 128 * DINc];          // W hi split [h][n][k]
__device__ __half g_W1[Hc * 128 * DINc];          // W lo split
__device__ float g_Sm[Bc * Hc * Tc];
__device__ float g_Su[Bc * Hc * Tc];
__device__ float g_Sw[Bc * Hc * Tc * Dc];
__device__ float g_Pm[Bc * Hc * NCc];
__device__ float g_Pu[Bc * Hc * NCc];
__device__ float g_Pw[Bc * Hc * NCc * Dc];

// ---------------- PTX helpers (baseline sm_80+ features only) ----------------
__device__ __forceinline__ uint32_t smem_u32(const void* p) {
    uint32_t a;
    asm("{ .reg .u64 t; cvta.to.shared.u64 t, %1; cvt.u32.u64 %0, t; }" : "=r"(a) : "l"(p));
    return a;
}
__device__ __forceinline__ void cp16(uint32_t dst, const void* src) {
    asm volatile("cp.async.cg.shared.global [%0], [%1], 16;" :: "r"(dst), "l"(src));
}
#define CP_COMMIT() asm volatile("cp.async.commit_group;" ::: "memory")
#define CP_WAIT2()  asm volatile("cp.async.wait_group 2;" ::: "memory")
#define CP_WAIT1()  asm volatile("cp.async.wait_group 1;" ::: "memory")
#define CP_WAIT0()  asm volatile("cp.async.wait_group 0;" ::: "memory")

#define LDSM4(r, addr) \
    asm volatile("ldmatrix.sync.aligned.m8n8.x4.shared.b16 {%0,%1,%2,%3}, [%4];" \
        : "=r"((r)[0]), "=r"((r)[1]), "=r"((r)[2]), "=r"((r)[3]) : "r"(addr))

#define MMA_F16(d, a0, a1, a2, a3, b0, b1) \
    asm volatile("mma.sync.aligned.m16n8k16.row.col.f32.f16.f16.f32 " \
        "{%0,%1,%2,%3}, {%4,%5,%6,%7}, {%8,%9}, {%0,%1,%2,%3};" \
        : "+f"((d)[0]), "+f"((d)[1]), "+f"((d)[2]), "+f"((d)[3]) \
        : "r"(a0), "r"(a1), "r"(a2), "r"(a3), "r"(b0), "r"(b1))

__device__ __forceinline__ unsigned h2u(__half2 v) {
    return *reinterpret_cast<unsigned*>(&v);
}
// XOR swizzle: byte offset of 16B chunk c in row r (64 B pitch)
__device__ __forceinline__ uint32_t swz(int row, int c) {
    return (uint32_t)(row * 64 + ((c ^ ((row >> 1) & 3)) << 4));
}

// ---------------------------------------------------------------------------
// prep: A fp32 -> fp16 (single); W fp32 -> fp16 hi/lo, transposed to [h][n][k].
// ---------------------------------------------------------------------------
__global__ __launch_bounds__(256)
void prep_split(const float* __restrict__ A, const float* __restrict__ W)
{
    if (blockIdx.x < 16384) {
        size_t i4 = ((size_t)blockIdx.x * 256 + threadIdx.x) * 4;
        float4 v = *reinterpret_cast<const float4*>(A + i4);
        uint2 o;
        o.x = h2u(__floats2half2_rn(v.x, v.y));
        o.y = h2u(__floats2half2_rn(v.z, v.w));
        *reinterpret_cast<uint2*>(reinterpret_cast<char*>(g_Ah) + i4 * 2) = o;
    } else {
        int idx = (blockIdx.x - 16384) * 256 + threadIdx.x;   // 0..524287
        int jg  = idx & 31;
        int h   = (idx >> 5) & 15;
        int k   = idx >> 9;
        float4 w = *reinterpret_cast<const float4*>(W + (size_t)k * (Hc * Dc * 2) + h * 128 + jg * 4);
        float x[4] = {w.x, w.y, w.z, w.w};
        #pragma unroll
        for (int e = 0; e < 4; ++e) {
            __half hb = __float2half_rn(x[e]);
            float hf = __half2float(hb);
            __half lb = __float2half_rn(x[e] - hf);
            size_t o = ((size_t)h * 128 + jg * 4 + e) * DINc + k;
            g_W0[o] = hb;
            g_W1[o] = lb;
        }
    }
}

// ---------------------------------------------------------------------------
// Kernel 1: fp16 2-term HMMA GEMM (kv = relu(A@(Wh+Wl))) + st=q.k + local scan.
// M=128, N=128, K=1024. 8 warps 4x2, warp tile 32x64. 4-stage cp.async
// pipeline, KC=32, XOR-swizzled 64B rows, 2 CTAs/SM.
// ---------------------------------------------------------------------------
__global__ __launch_bounds__(256, 2)
void k1_gemm_scan(const float* __restrict__ Q)
{
    extern __shared__ __align__(1024) char dsm[];
    const int h = blockIdx.x, c = blockIdx.y, b = blockIdx.z;
    const int t0 = c * TCc;
    const int tid = threadIdx.x;
    const int wid = tid >> 5, lane = tid & 31;
    const int wm = wid >> 1;           // 0..3 (M groups of 32)
    const int wn = wid & 1;            // 0..1 (N groups of 64)
    const uint32_t sb = smem_u32(dsm);

    float* qS = (float*)(dsm + 32);
    if (tid < 64) qS[tid] = Q[h * Dc + tid];

    const __half* Ab  = g_Ah + ((size_t)b * Tc + t0) * DINc;
    const __half* Wb0 = g_W0 + (size_t)h * 128 * DINc;
    const __half* Wb1 = g_W1 + (size_t)h * 128 * DINc;

    const int ld_row = tid >> 1;
    const int ld_c0  = (tid & 1) * 2;

    float acc[2][8][4];
    #pragma unroll
    for (int mt = 0; mt < 2; ++mt)
        #pragma unroll
        for (int nt = 0; nt < 8; ++nt)
            #pragma unroll
            for (int e = 0; e < 4; ++e) acc[mt][nt][e] = 0.f;

    #define ISSUE_STAGE(SIDX)                                                     \
    do {                                                                          \
        uint32_t stg_ = sb + 1024 + ((SIDX) % NBUF) * STG_B;                      \
        const int k0_ = (SIDX) * KC;                                              \
        size_t so0 = (size_t)ld_row * DINc + k0_ + ld_c0 * 8;                     \
        uint32_t d0 = stg_ + swz(ld_row, ld_c0);                                  \
        uint32_t d1 = stg_ + swz(ld_row, ld_c0 + 1);                              \
        cp16(d0 + A_OFF,  Ab  + so0);  cp16(d1 + A_OFF,  Ab  + so0 + 8);          \
        cp16(d0 + B0_OFF, Wb0 + so0);  cp16(d1 + B0_OFF, Wb0 + so0 + 8);          \
        cp16(d0 + B1_OFF, Wb1 + so0);  cp16(d1 + B1_OFF, Wb1 + so0 + 8);          \
        CP_COMMIT();                                                              \
    } while (0)

    ISSUE_STAGE(0);
    ISSUE_STAGE(1);
    ISSUE_STAGE(2);

    for (int i = 0; i < NST; ++i) {
        if (i + 2 < NST)      CP_WAIT2();
        else if (i + 1 < NST) CP_WAIT1();
        else                  CP_WAIT0();
        __syncthreads();
        if (i + 3 < NST) ISSUE_STAGE(i + 3);

        const uint32_t stg = sb + 1024 + (i % NBUF) * STG_B;
        #pragma unroll
        for (int ks = 0; ks < 2; ++ks) {
            uint32_t aT[2][4];
            #pragma unroll
            for (int mt = 0; mt < 2; ++mt) {
                int row = wm * 32 + mt * 16 + (lane & 15);
                int cc = ks * 2 + (lane >> 4);
                LDSM4(aT[mt], stg + swz(row, cc) + A_OFF);
            }
            #pragma unroll
            for (int nt2 = 0; nt2 < 4; ++nt2) {
                int row = wn * 64 + nt2 * 16 + (lane & 7) + ((lane >> 4) << 3);
                int cc = ks * 2 + ((lane >> 3) & 1);
                uint32_t bd = stg + swz(row, cc);
                uint32_t rH[4], rL[4];
                LDSM4(rH, bd + B0_OFF);
                LDSM4(rL, bd + B1_OFF);
                // 4 independent accumulators between RAW reuses
                #pragma unroll
                for (int mt = 0; mt < 2; ++mt) {
                    MMA_F16(acc[mt][2 * nt2],     aT[mt][0], aT[mt][1], aT[mt][2], aT[mt][3], rH[0], rH[1]);
                    MMA_F16(acc[mt][2 * nt2 + 1], aT[mt][0], aT[mt][1], aT[mt][2], aT[mt][3], rH[2], rH[3]);
                }
                #pragma unroll
                for (int mt = 0; mt < 2; ++mt) {
                    MMA_F16(acc[mt][2 * nt2],     aT[mt][0], aT[mt][1], aT[mt][2], aT[mt][3], rL[0], rL[1]);
                    MMA_F16(acc[mt][2 * nt2 + 1], aT[mt][0], aT[mt][1], aT[mt][2], aT[mt][3], rL[2], rL[3]);
                }
            }
        }
    }
    __syncthreads();

    // ---------------- epilogue: relu, st = q.k partials, Vs ----------------
    float* Vs     = (float*)(dsm + 1024);                      // [128][65]
    float* stS    = (float*)(dsm + 1024 + 128 * 65 * 4);       // [128]
    float* stPart = (float*)(dsm + 1024 + 128 * 65 * 4 + 512); // [128][8]

    const int g = lane >> 2;
    const int dq = lane & 3;
    #pragma unroll
    for (int mt = 0; mt < 2; ++mt) {
        const int m0 = wm * 32 + mt * 16 + g;
        float stp0 = 0.f, stp1 = 0.f;
        #pragma unroll
        for (int nt = 0; nt < 8; ++nt) {
            int d = wn * 32 + nt * 4 + dq;
            float qd = qS[d];
            float k0_ = fmaxf(acc[mt][nt][0], 0.f);
            float v0_ = fmaxf(acc[mt][nt][1], 0.f);
            float k1_ = fmaxf(acc[mt][nt][2], 0.f);
            float v1_ = fmaxf(acc[mt][nt][3], 0.f);
            stp0 = fmaf(qd, k0_, stp0);
            stp1 = fmaf(qd, k1_, stp1);
            Vs[m0 * 65 + d]       = v0_;
            Vs[(m0 + 8) * 65 + d] = v1_;
        }
        stPart[m0 * 8 + wn * 4 + dq]       = stp0;
        stPart[(m0 + 8) * 8 + wn * 4 + dq] = stp1;
    }
    __syncthreads();

    if (tid < 128) {
        float s = 0.f;
        #pragma unroll
        for (int x = 0; x < 8; ++x) s += stPart[tid * 8 + x];
        stS[tid] = s;
    }
    __syncthreads();

    // ---------------- sequential local scan over the chunk ----------------
    if (tid < Dc) {
        const int sl = tid;
        const size_t baseT = ((size_t)(b * Hc + h)) * Tc + t0;
        float m = -FLT_MAX, u = 0.f, w = 0.f;
        for (int t = 0; t < TCc; ++t) {
            float st = stS[t];
            float mn = fmaxf(m, st);
            float ea = __expf(m - mn);
            float eb = __expf(st - mn);
            u = u * ea + eb;
            w = fmaf(w, ea, Vs[t * 65 + sl] * eb);
            m = mn;
            g_Sw[(baseT + t) * Dc + sl] = w;
            if (sl == 0) { g_Sm[baseT + t] = m; g_Su[baseT + t] = u; }
        }
    }
}

// ---------------------------------------------------------------------------
// Kernel 2: exclusive prefix over chunk summaries per (b,h).
// ---------------------------------------------------------------------------
__global__ void k2_prefix()
{
    const int bh = blockIdx.x;
    const int lane = threadIdx.x;
    const size_t baseT = (size_t)bh * Tc;
    const size_t baseC = (size_t)bh * NCc;

    float sm[NCc], su[NCc], sw[NCc];
    #pragma unroll
    for (int cI = 0; cI < NCc; ++cI) {
        int t = cI * TCc + (TCc - 1);
        sm[cI] = g_Sm[baseT + t];
        su[cI] = g_Su[baseT + t];
        sw[cI] = g_Sw[(baseT + t) * Dc + lane];
    }
    float m = -FLT_MAX, u = 0.f, w = 0.f;
    #pragma unroll
    for (int cI = 0; cI < NCc; ++cI) {
        g_Pw[(baseC + cI) * Dc + lane] = w;
        if (lane == 0) { g_Pm[baseC + cI] = m; g_Pu[baseC + cI] = u; }
        float mn = fmaxf(m, sm[cI]);
        float ea = __expf(m - mn);
        float eb = __expf(sm[cI] - mn);
        u = u * ea + su[cI] * eb;
        w = fmaf(w, ea, sw[cI] * eb);
        m = mn;
    }
}

// ---------------------------------------------------------------------------
// Kernel 3: combine prefix + local, h = w/u, sum over heads.
// Block = 8 rows sharing (b, chunk), 512 threads. Scalars+Pw staged once.
// ---------------------------------------------------------------------------
__global__ __launch_bounds__(512)
void k3_final(float* __restrict__ out)
{
    __shared__ float sPw[Hc][Dc];
    __shared__ float sPm[Hc], sPu[Hc];
    __shared__ float sSm[8][Hc], sSu[8][Hc];

    const int tid = threadIdx.x;
    const size_t row0 = (size_t)blockIdx.x * 8;      // 8 rows, same b, same chunk
    const int b  = (int)(row0 >> 12);
    const int t0 = (int)(row0 & 4095);
    const int cI = t0 / TCc;

    // cooperative staging
    for (int i = tid; i < Hc * Dc; i += 512) {
        int hh = i >> 6, d = i & 63;
        sPw[hh][d] = g_Pw[(((size_t)b * Hc + hh) * NCc + cI) * Dc + d];
    }
    if (tid < Hc) {
        size_t ci = ((size_t)b * Hc + tid) * NCc + cI;
        sPm[tid] = g_Pm[ci];
        sPu[tid] = g_Pu[ci];
    } else if (tid < 16 + 128) {
        int j = tid - 16; int r = j >> 4, hh = j & 15;
        sSm[r][hh] = g_Sm[((size_t)b * Hc + hh) * Tc + t0 + r];
    } else if (tid < 144 + 128) {
        int j = tid - 144; int r = j >> 4, hh = j & 15;
        sSu[r][hh] = g_Su[((size_t)b * Hc + hh) * Tc + t0 + r];
    }
    __syncthreads();

    const int r = tid >> 6, lane = tid & 63;
    const int t = t0 + r;
    float acc = 0.f;
    #pragma unroll
    for (int hh = 0; hh < Hc; ++hh) {
        size_t ti = ((size_t)b * Hc + hh) * Tc + t;
        float lw = g_Sw[ti * Dc + lane];
        float pm = sPm[hh], pu = sPu[hh];
        float lm = sSm[r][hh], lu = sSu[r][hh];
        float mn = fmaxf(pm, lm);
        float ea = __expf(pm - mn);
        float eb = __expf(lm - mn);
        float u = pu * ea + lu * eb;
        float w = fmaf(sPw[hh][lane], ea, lw * eb);
        acc += __fdividef(w, u);
    }
    out[(row0 + r) * Dc + lane] = acc;
}

// ---------------------------------------------------------------------------
extern "C" void kernel_launch(void* const* d_in, const int* in_sizes, int n_in,
                              void* d_out, int out_size)
{
    const float* A = nullptr;
    const float* W = nullptr;
    const float* Q = nullptr;
    for (int i = 0; i < n_in; ++i) {
        if      (in_sizes[i] == Bc * Tc * DINc)      A = (const float*)d_in[i];
        else if (in_sizes[i] == DINc * Hc * Dc * 2)  W = (const float*)d_in[i];
        else if (in_sizes[i] == Hc * Dc)             Q = (const float*)d_in[i];
    }
    float* out = (float*)d_out;

    cudaFuncSetAttribute(k1_gemm_scan, cudaFuncAttributeMaxDynamicSharedMemorySize, SMEM_DYN);

    prep_split<<<16384 + 2048, 256>>>(A, W);
    dim3 g1(Hc, NCc, Bc);
    k1_gemm_scan<<<g1, 256, SMEM_DYN>>>(Q);
    k2_prefix<<<Bc * Hc, Dc>>>();
    k3_final<<<(Bc * Tc) / 8, 512>>>(out);
}

// round 15
// speedup vs baseline: 2.2200x; 1.5989x over previous
#include <cuda_runtime.h>
#include <cuda_fp16.h>
#include <float.h>
#include <math.h>
#include <stdint.h>

// Problem constants
#define Bc   4
#define Tc   4096
#define DINc 1024
#define Hc   16
#define Dc   64
#define TCc  128            // t-chunk (M) per block
#define NCc  (Tc / TCc)     // 32 chunks
#define KC   32             // K per stage
#define NST  (DINc / KC)    // 32 stages

// SMEM stage: 2 matrices of [128 rows][32 fp16] (64 B rows, XOR-swizzled)
#define MAT_B  (128 * 64)                  // 8192
#define A_OFF  0
#define B_OFF  MAT_B
#define STG_B  (2 * MAT_B)                 // 16384
#define NBUF   6
#define SMEM_DYN (1024 + NBUF * STG_B)     // 99328 -> 2 CTAs/SM

// Scratch (allocation-free rule: __device__ globals)
__device__ __half g_Ah[Bc * Tc * DINc];           // inputs fp16 [b*t][k]
__device__ __half g_Wh[Hc * 128 * DINc];          // W fp16 [h][n][k]
__device__ float g_Sm[Bc * Hc * Tc];
__device__ float g_Su[Bc * Hc * Tc];
__device__ float g_Sw[Bc * Hc * Tc * Dc];
__device__ float g_Pm[Bc * Hc * NCc];
__device__ float g_Pu[Bc * Hc * NCc];
__device__ float g_Pw[Bc * Hc * NCc * Dc];

// ---------------- PTX helpers (baseline sm_80+ features only) ----------------
__device__ __forceinline__ uint32_t smem_u32(const void* p) {
    uint32_t a;
    asm("{ .reg .u64 t; cvta.to.shared.u64 t, %1; cvt.u32.u64 %0, t; }" : "=r"(a) : "l"(p));
    return a;
}
__device__ __forceinline__ void cp16(uint32_t dst, const void* src) {
    asm volatile("cp.async.cg.shared.global [%0], [%1], 16;" :: "r"(dst), "l"(src));
}
#define CP_COMMIT() asm volatile("cp.async.commit_group;" ::: "memory")
#define CP_WAIT4()  asm volatile("cp.async.wait_group 4;" ::: "memory")
#define CP_WAIT3()  asm volatile("cp.async.wait_group 3;" ::: "memory")
#define CP_WAIT2()  asm volatile("cp.async.wait_group 2;" ::: "memory")
#define CP_WAIT1()  asm volatile("cp.async.wait_group 1;" ::: "memory")
#define CP_WAIT0()  asm volatile("cp.async.wait_group 0;" ::: "memory")

#define LDSM4(r, addr) \
    asm volatile("ldmatrix.sync.aligned.m8n8.x4.shared.b16 {%0,%1,%2,%3}, [%4];" \
        : "=r"((r)[0]), "=r"((r)[1]), "=r"((r)[2]), "=r"((r)[3]) : "r"(addr))

#define MMA_F16(d, a0, a1, a2, a3, b0, b1) \
    asm volatile("mma.sync.aligned.m16n8k16.row.col.f32.f16.f16.f32 " \
        "{%0,%1,%2,%3}, {%4,%5,%6,%7}, {%8,%9}, {%0,%1,%2,%3};" \
        : "+f"((d)[0]), "+f"((d)[1]), "+f"((d)[2]), "+f"((d)[3]) \
        : "r"(a0), "r"(a1), "r"(a2), "r"(a3), "r"(b0), "r"(b1))

__device__ __forceinline__ unsigned h2u(__half2 v) {
    return *reinterpret_cast<unsigned*>(&v);
}
// XOR swizzle: byte offset of 16B chunk c in row r (64 B pitch)
__device__ __forceinline__ uint32_t swz(int row, int c) {
    return (uint32_t)(row * 64 + ((c ^ ((row >> 1) & 3)) << 4));
}

// ---------------------------------------------------------------------------
// prep: A fp32 -> fp16; W fp32 -> fp16, transposed to [h][n][k].
// ---------------------------------------------------------------------------
__global__ __launch_bounds__(256)
void prep_split(const float* __restrict__ A, const float* __restrict__ W)
{
    if (blockIdx.x < 16384) {
        size_t i4 = ((size_t)blockIdx.x * 256 + threadIdx.x) * 4;
        float4 v = *reinterpret_cast<const float4*>(A + i4);
        uint2 o;
        o.x = h2u(__floats2half2_rn(v.x, v.y));
        o.y = h2u(__floats2half2_rn(v.z, v.w));
        *reinterpret_cast<uint2*>(reinterpret_cast<char*>(g_Ah) + i4 * 2) = o;
    } else {
        int idx = (blockIdx.x - 16384) * 256 + threadIdx.x;   // 0..524287
        int jg  = idx & 31;
        int h   = (idx >> 5) & 15;
        int k   = idx >> 9;
        float4 w = *reinterpret_cast<const float4*>(W + (size_t)k * (Hc * Dc * 2) + h * 128 + jg * 4);
        float x[4] = {w.x, w.y, w.z, w.w};
        #pragma unroll
        for (int e = 0; e < 4; ++e)
            g_Wh[((size_t)h * 128 + jg * 4 + e) * DINc + k] = __float2half_rn(x[e]);
    }
}

// ---------------------------------------------------------------------------
// Kernel 1: single-term fp16 HMMA GEMM (kv = relu(A@W)) + st=q.k + local scan.
// M=128, N=128, K=1024. 8 warps 4x2, warp tile 32x64. 6-stage cp.async
// pipeline, KC=32, XOR-swizzled 64B rows, 2 CTAs/SM.
// ---------------------------------------------------------------------------
__global__ __launch_bounds__(256, 2)
void k1_gemm_scan(const float* __restrict__ Q)
{
    extern __shared__ __align__(1024) char dsm[];
    const int h = blockIdx.x, c = blockIdx.y, b = blockIdx.z;
    const int t0 = c * TCc;
    const int tid = threadIdx.x;
    const int wid = tid >> 5, lane = tid & 31;
    const int wm = wid >> 1;           // 0..3 (M groups of 32)
    const int wn = wid & 1;            // 0..1 (N groups of 64)
    const uint32_t sb = smem_u32(dsm);

    float* qS = (float*)(dsm + 32);
    if (tid < 64) qS[tid] = Q[h * Dc + tid];

    const __half* Ab = g_Ah + ((size_t)b * Tc + t0) * DINc;
    const __half* Wb = g_Wh + (size_t)h * 128 * DINc;

    const int ld_row = tid >> 1;
    const int ld_c0  = (tid & 1) * 2;

    float acc[2][8][4];
    #pragma unroll
    for (int mt = 0; mt < 2; ++mt)
        #pragma unroll
        for (int nt = 0; nt < 8; ++nt)
            #pragma unroll
            for (int e = 0; e < 4; ++e) acc[mt][nt][e] = 0.f;

    #define ISSUE_STAGE(SIDX)                                                     \
    do {                                                                          \
        uint32_t stg_ = sb + 1024 + ((SIDX) % NBUF) * STG_B;                      \
        const int k0_ = (SIDX) * KC;                                              \
        size_t so0 = (size_t)ld_row * DINc + k0_ + ld_c0 * 8;                     \
        uint32_t d0 = stg_ + swz(ld_row, ld_c0);                                  \
        uint32_t d1 = stg_ + swz(ld_row, ld_c0 + 1);                              \
        cp16(d0 + A_OFF, Ab + so0);  cp16(d1 + A_OFF, Ab + so0 + 8);              \
        cp16(d0 + B_OFF, Wb + so0);  cp16(d1 + B_OFF, Wb + so0 + 8);              \
        CP_COMMIT();                                                              \
    } while (0)

    ISSUE_STAGE(0);
    ISSUE_STAGE(1);
    ISSUE_STAGE(2);
    ISSUE_STAGE(3);
    ISSUE_STAGE(4);

    for (int i = 0; i < NST; ++i) {
        // wait until stage i's group has landed (keep up to 4 groups in flight)
        if      (i + 5 <= NST - 1) CP_WAIT4();
        else if (i + 4 <= NST - 1) CP_WAIT3();
        else if (i + 3 <= NST - 1) CP_WAIT2();
        else if (i + 2 <= NST - 1) CP_WAIT1();
        else                       CP_WAIT0();
        __syncthreads();              // all warps done with stage i-1's buffer
        if (i + 5 < NST) ISSUE_STAGE(i + 5);

        const uint32_t stg = sb + 1024 + (i % NBUF) * STG_B;
        #pragma unroll
        for (int ks = 0; ks < 2; ++ks) {
            uint32_t aT[2][4];
            #pragma unroll
            for (int mt = 0; mt < 2; ++mt) {
                int row = wm * 32 + mt * 16 + (lane & 15);
                int cc = ks * 2 + (lane >> 4);
                LDSM4(aT[mt], stg + swz(row, cc) + A_OFF);
            }
            #pragma unroll
            for (int nt2 = 0; nt2 < 4; ++nt2) {
                int row = wn * 64 + nt2 * 16 + (lane & 7) + ((lane >> 4) << 3);
                int cc = ks * 2 + ((lane >> 3) & 1);
                uint32_t rB[4];
                LDSM4(rB, stg + swz(row, cc) + B_OFF);
                // 4 independent accumulators between RAW reuses
                #pragma unroll
                for (int mt = 0; mt < 2; ++mt) {
                    MMA_F16(acc[mt][2 * nt2],     aT[mt][0], aT[mt][1], aT[mt][2], aT[mt][3], rB[0], rB[1]);
                    MMA_F16(acc[mt][2 * nt2 + 1], aT[mt][0], aT[mt][1], aT[mt][2], aT[mt][3], rB[2], rB[3]);
                }
            }
        }
    }
    __syncthreads();

    // ---------------- epilogue: relu, st = q.k partials, Vs ----------------
    float* Vs     = (float*)(dsm + 1024);                      // [128][65]
    float* stS    = (float*)(dsm + 1024 + 128 * 65 * 4);       // [128]
    float* stPart = (float*)(dsm + 1024 + 128 * 65 * 4 + 512); // [128][8]

    const int g = lane >> 2;
    const int dq = lane & 3;
    #pragma unroll
    for (int mt = 0; mt < 2; ++mt) {
        const int m0 = wm * 32 + mt * 16 + g;
        float stp0 = 0.f, stp1 = 0.f;
        #pragma unroll
        for (int nt = 0; nt < 8; ++nt) {
            int d = wn * 32 + nt * 4 + dq;
            float qd = qS[d];
            float k0_ = fmaxf(acc[mt][nt][0], 0.f);
            float v0_ = fmaxf(acc[mt][nt][1], 0.f);
            float k1_ = fmaxf(acc[mt][nt][2], 0.f);
            float v1_ = fmaxf(acc[mt][nt][3], 0.f);
            stp0 = fmaf(qd, k0_, stp0);
            stp1 = fmaf(qd, k1_, stp1);
            Vs[m0 * 65 + d]       = v0_;
            Vs[(m0 + 8) * 65 + d] = v1_;
        }
        stPart[m0 * 8 + wn * 4 + dq]       = stp0;
        stPart[(m0 + 8) * 8 + wn * 4 + dq] = stp1;
    }
    __syncthreads();

    if (tid < 128) {
        float s = 0.f;
        #pragma unroll
        for (int x = 0; x < 8; ++x) s += stPart[tid * 8 + x];
        stS[tid] = s;
    }
    __syncthreads();

    // ---------------- sequential local scan over the chunk ----------------
    if (tid < Dc) {
        const int sl = tid;
        const size_t baseT = ((size_t)(b * Hc + h)) * Tc + t0;
        float m = -FLT_MAX, u = 0.f, w = 0.f;
        for (int t = 0; t < TCc; ++t) {
            float st = stS[t];
            float mn = fmaxf(m, st);
            float ea = __expf(m - mn);
            float eb = __expf(st - mn);
            u = u * ea + eb;
            w = fmaf(w, ea, Vs[t * 65 + sl] * eb);
            m = mn;
            g_Sw[(baseT + t) * Dc + sl] = w;
            if (sl == 0) { g_Sm[baseT + t] = m; g_Su[baseT + t] = u; }
        }
    }
}

// ---------------------------------------------------------------------------
// Kernel 2: exclusive prefix over chunk summaries per (b,h).
// ---------------------------------------------------------------------------
__global__ void k2_prefix()
{
    const int bh = blockIdx.x;
    const int lane = threadIdx.x;
    const size_t baseT = (size_t)bh * Tc;
    const size_t baseC = (size_t)bh * NCc;

    float sm[NCc], su[NCc], sw[NCc];
    #pragma unroll
    for (int cI = 0; cI < NCc; ++cI) {
        int t = cI * TCc + (TCc - 1);
        sm[cI] = g_Sm[baseT + t];
        su[cI] = g_Su[baseT + t];
        sw[cI] = g_Sw[(baseT + t) * Dc + lane];
    }
    float m = -FLT_MAX, u = 0.f, w = 0.f;
    #pragma unroll
    for (int cI = 0; cI < NCc; ++cI) {
        g_Pw[(baseC + cI) * Dc + lane] = w;
        if (lane == 0) { g_Pm[baseC + cI] = m; g_Pu[baseC + cI] = u; }
        float mn = fmaxf(m, sm[cI]);
        float ea = __expf(m - mn);
        float eb = __expf(sm[cI] - mn);
        u = u * ea + su[cI] * eb;
        w = fmaf(w, ea, sw[cI] * eb);
        m = mn;
    }
}

// ---------------------------------------------------------------------------
// Kernel 3: combine prefix + local, h = w/u, sum over heads.
// Block = 8 rows sharing (b, chunk), 512 threads. Scalars+Pw staged once.
// ---------------------------------------------------------------------------
__global__ __launch_bounds__(512)
void k3_final(float* __restrict__ out)
{
    __shared__ float sPw[Hc][Dc];
    __shared__ float sPm[Hc], sPu[Hc];
    __shared__ float sSm[8][Hc], sSu[8][Hc];

    const int tid = threadIdx.x;
    const size_t row0 = (size_t)blockIdx.x * 8;      // 8 rows, same b, same chunk
    const int b  = (int)(row0 >> 12);
    const int t0 = (int)(row0 & 4095);
    const int cI = t0 / TCc;

    // cooperative staging
    for (int i = tid; i < Hc * Dc; i += 512) {
        int hh = i >> 6, d = i & 63;
        sPw[hh][d] = g_Pw[(((size_t)b * Hc + hh) * NCc + cI) * Dc + d];
    }
    if (tid < Hc) {
        size_t ci = ((size_t)b * Hc + tid) * NCc + cI;
        sPm[tid] = g_Pm[ci];
        sPu[tid] = g_Pu[ci];
    } else if (tid < 16 + 128) {
        int j = tid - 16; int r = j >> 4, hh = j & 15;
        sSm[r][hh] = g_Sm[((size_t)b * Hc + hh) * Tc + t0 + r];
    } else if (tid < 144 + 128) {
        int j = tid - 144; int r = j >> 4, hh = j & 15;
        sSu[r][hh] = g_Su[((size_t)b * Hc + hh) * Tc + t0 + r];
    }
    __syncthreads();

    const int r = tid >> 6, lane = tid & 63;
    const int t = t0 + r;
    float acc = 0.f;
    #pragma unroll
    for (int hh = 0; hh < Hc; ++hh) {
        size_t ti = ((size_t)b * Hc + hh) * Tc + t;
        float lw = g_Sw[ti * Dc + lane];
        float pm = sPm[hh], pu = sPu[hh];
        float lm = sSm[r][hh], lu = sSu[r][hh];
        float mn = fmaxf(pm, lm);
        float ea = __expf(pm - mn);
        float eb = __expf(lm - mn);
        float u = pu * ea + lu * eb;
        float w = fmaf(sPw[hh][lane], ea, lw * eb);
        acc += __fdividef(w, u);
    }
    out[(row0 + r) * Dc + lane] = acc;
}

// ---------------------------------------------------------------------------
extern "C" void kernel_launch(void* const* d_in, const int* in_sizes, int n_in,
                              void* d_out, int out_size)
{
    const float* A = nullptr;
    const float* W = nullptr;
    const float* Q = nullptr;
    for (int i = 0; i < n_in; ++i) {
        if      (in_sizes[i] == Bc * Tc * DINc)      A = (const float*)d_in[i];
        else if (in_sizes[i] == DINc * Hc * Dc * 2)  W = (const float*)d_in[i];
        else if (in_sizes[i] == Hc * Dc)             Q = (const float*)d_in[i];
    }
    float* out = (float*)d_out;

    cudaFuncSetAttribute(k1_gemm_scan, cudaFuncAttributeMaxDynamicSharedMemorySize, SMEM_DYN);

    prep_split<<<16384 + 2048, 256>>>(A, W);
    dim3 g1(Hc, NCc, Bc);
    k1_gemm_scan<<<g1, 256, SMEM_DYN>>>(Q);
    k2_prefix<<<Bc * Hc, Dc>>>();
    k3_final<<<(Bc * Tc) / 8, 512>>>(out);
}